// round 14
// baseline (speedup 1.0000x reference)
#include <cuda_runtime.h>
#include <cuda_bf16.h>
#include <math.h>
#include <stdint.h>

#define N_NODES    50000
#define N_EDGES    600000
#define DIM        128
#define VOCAB      20215
#define NUM_GRAPHS 512
#define PTILES     ((VOCAB + 63) / 64)     // 316
#define ROWB2      272                     // 128 bf16 = 256B + 16 pad; LDSM conflict-free
#define P_OFF_W    0                       // 256 x 272 = 69632
#define P_OFF_A    69632                   // 64 x 272  = 17408
#define P_SMEM     (69632 + 17408)

// Scratch (device globals: allocation inside kernel_launch is forbidden)
__device__ __align__(16) float g_agg[N_NODES * DIM];          // normalized agg @ Wl^T
__device__ __align__(16) __nv_bfloat16 g_embWl_bf[VOCAB * DIM];
__device__ __align__(16) float g_embWr[VOCAB * DIM];
__device__ int g_cnt[N_NODES];     // in-degree
__device__ int g_off[N_NODES];     // CSR offsets
__device__ int g_cur[N_NODES];     // fill cursors
__device__ int g_csr[N_EDGES];     // token id of src, grouped by dst
__device__ int g_seg[NUM_GRAPHS];

// ---- warp-MMA helpers (sm_80-era PTX, valid for compute_100) ---------------
__device__ __forceinline__ uint32_t smem_u32(const void* p) {
    uint32_t a;
    asm("{ .reg .u64 t; cvta.to.shared.u64 t, %1; cvt.u32.u64 %0, t; }"
        : "=r"(a) : "l"(p));
    return a;
}
__device__ __forceinline__ void ldsm_x4(uint32_t* r, uint32_t addr) {
    asm volatile("ldmatrix.sync.aligned.m8n8.x4.shared.b16 {%0,%1,%2,%3}, [%4];"
                 : "=r"(r[0]), "=r"(r[1]), "=r"(r[2]), "=r"(r[3]) : "r"(addr));
}
__device__ __forceinline__ void ldsm_x2(uint32_t* r, uint32_t addr) {
    asm volatile("ldmatrix.sync.aligned.m8n8.x2.shared.b16 {%0,%1}, [%2];"
                 : "=r"(r[0]), "=r"(r[1]) : "r"(addr));
}
__device__ __forceinline__ void mma16816(float* c, const uint32_t* a, const uint32_t* b) {
    asm volatile(
        "mma.sync.aligned.m16n8k16.row.col.f32.bf16.bf16.f32 "
        "{%0,%1,%2,%3}, {%4,%5,%6,%7}, {%8,%9}, {%0,%1,%2,%3};"
        : "+f"(c[0]), "+f"(c[1]), "+f"(c[2]), "+f"(c[3])
        : "r"(a[0]), "r"(a[1]), "r"(a[2]), "r"(a[3]), "r"(b[0]), "r"(b[1]));
}
__device__ __forceinline__ uint4 pack_bf16x8(const float* f) {
    __nv_bfloat162 h0 = __float22bfloat162_rn(make_float2(f[0], f[1]));
    __nv_bfloat162 h1 = __float22bfloat162_rn(make_float2(f[2], f[3]));
    __nv_bfloat162 h2 = __float22bfloat162_rn(make_float2(f[4], f[5]));
    __nv_bfloat162 h3 = __float22bfloat162_rn(make_float2(f[6], f[7]));
    uint4 u;
    u.x = *reinterpret_cast<uint32_t*>(&h0);
    u.y = *reinterpret_cast<uint32_t*>(&h1);
    u.z = *reinterpret_cast<uint32_t*>(&h2);
    u.w = *reinterpret_cast<uint32_t*>(&h3);
    return u;
}

// ---------------------------------------------------------------------------
__global__ void zero_kernel() {
    int i = blockIdx.x * blockDim.x + threadIdx.x;
    int stride = gridDim.x * blockDim.x;
    for (int k = i; k < N_NODES; k += stride) {
        g_cnt[k] = 0;
        g_cur[k] = 0;
    }
}

__global__ void seg_kernel(const int* __restrict__ batch) {
    int i = blockIdx.x * blockDim.x + threadIdx.x;
    int stride = gridDim.x * blockDim.x;
    for (; i < N_NODES; i += stride) {
        if (i == 0 || batch[i] != batch[i - 1]) g_seg[batch[i]] = i;
    }
}

// ---------------------------------------------------------------------------
// K2: precompute embWl (bf16) and embWr (fp32) via bf16 warp-MMA.
// ---------------------------------------------------------------------------
__global__ void __launch_bounds__(128, 1)
precompute_kernel(const float* __restrict__ emb,
                  const float* __restrict__ Wl,
                  const float* __restrict__ Wr) {
    extern __shared__ char dyn[];
    char* sW = dyn + P_OFF_W;            // [256 n][128 k] bf16, stride 272B
    char* sA = dyn + P_OFF_A;            // [64 v][128 k] bf16, stride 272B

    const int t    = threadIdx.x;
    const int wid  = t >> 5;
    const int lane = t & 31;

    // Stage W' = [Wl; Wr]: 256 rows x 128 k
    for (int j = 0; j < 32; j++) {
        int chunk = t + j * 128;
        int n  = chunk >> 4;
        int ck = (chunk & 15) * 8;
        const float* src = (n < DIM) ? (Wl + n * DIM + ck)
                                     : (Wr + (n - DIM) * DIM + ck);
        float f[8];
        *reinterpret_cast<float4*>(f)     = *reinterpret_cast<const float4*>(src);
        *reinterpret_cast<float4*>(f + 4) = *reinterpret_cast<const float4*>(src + 4);
        *reinterpret_cast<uint4*>(sW + n * ROWB2 + ck * 2) = pack_bf16x8(f);
    }

    const int tbase = blockIdx.x * 64;
    for (int j = 0; j < 8; j++) {
        int chunk = t + j * 128;
        int r  = chunk >> 4;
        int ck = (chunk & 15) * 8;
        int v  = tbase + r;
        float f[8];
#pragma unroll
        for (int i = 0; i < 8; i++) f[i] = 0.f;
        if (v < VOCAB) {
            const float4* s4 = reinterpret_cast<const float4*>(
                emb + (size_t)v * DIM + ck);
            *reinterpret_cast<float4*>(f)     = s4[0];
            *reinterpret_cast<float4*>(f + 4) = s4[1];
        }
        *reinterpret_cast<uint4*>(sA + r * ROWB2 + ck * 2) = pack_bf16x8(f);
    }
    __syncthreads();

    const uint32_t sA_base = smem_u32(sA);
    const uint32_t sW_base = smem_u32(sW);
    const uint32_t a_lane_off = (uint32_t)((wid * 16 + (lane & 15)) * ROWB2
                                           + ((lane >> 4) * 8) * 2);
    const uint32_t b_lane_off = (uint32_t)((lane & 7) * ROWB2
                                           + ((lane >> 3) & 1) * 16);

    float acc[32][4];
#pragma unroll
    for (int n = 0; n < 32; n++)
#pragma unroll
        for (int i = 0; i < 4; i++) acc[n][i] = 0.f;

    for (int kk = 0; kk < 8; kk++) {
        uint32_t a[4];
        ldsm_x4(a, sA_base + a_lane_off + kk * 32);
#pragma unroll
        for (int n = 0; n < 32; n++) {
            uint32_t b[2];
            ldsm_x2(b, sW_base + (uint32_t)(n * 8 * ROWB2) + b_lane_off + kk * 32);
            mma16816(acc[n], a, b);
        }
    }

    // cols 0..127 -> embWl (bf16), 128..255 -> embWr (fp32)
    const int row = wid * 16 + (lane >> 2);
    const int v0 = tbase + row;
    const int v1 = v0 + 8;
#pragma unroll
    for (int n = 0; n < 32; n++) {
        int col = (n & 15) * 8 + (lane & 3) * 2;
        if (n < 16) {
            __nv_bfloat162 p0 = __float22bfloat162_rn(
                make_float2(acc[n][0], acc[n][1]));
            __nv_bfloat162 p1 = __float22bfloat162_rn(
                make_float2(acc[n][2], acc[n][3]));
            if (v0 < VOCAB)
                *reinterpret_cast<__nv_bfloat162*>(
                    &g_embWl_bf[(size_t)v0 * DIM + col]) = p0;
            if (v1 < VOCAB)
                *reinterpret_cast<__nv_bfloat162*>(
                    &g_embWl_bf[(size_t)v1 * DIM + col]) = p1;
        } else {
            if (v0 < VOCAB)
                *reinterpret_cast<float2*>(g_embWr + (size_t)v0 * DIM + col) =
                    make_float2(acc[n][0], acc[n][1]);
            if (v1 < VOCAB)
                *reinterpret_cast<float2*>(g_embWr + (size_t)v1 * DIM + col) =
                    make_float2(acc[n][2], acc[n][3]);
        }
    }
}

// ---------------------------------------------------------------------------
// CSR build: histogram -> single-block scan -> fill (token ids, dst-grouped)
// ---------------------------------------------------------------------------
__global__ void hist_kernel(const int* __restrict__ ei) {
    int e = blockIdx.x * blockDim.x + threadIdx.x;
    if (e < N_EDGES) atomicAdd(&g_cnt[ei[N_EDGES + e]], 1);
}

__global__ void __launch_bounds__(1024) scan_kernel() {
    __shared__ int sp[1024];
    const int T = 1024;
    const int t = threadIdx.x;
    const int chunk = (N_NODES + T - 1) / T;   // 49
    const int lo = t * chunk;
    const int hi = min(lo + chunk, N_NODES);
    int s = 0;
    for (int i = lo; i < hi; i++) s += g_cnt[i];
    sp[t] = s;
    __syncthreads();
    int own = s;
    for (int o = 1; o < T; o <<= 1) {
        int v = (t >= o) ? sp[t - o] : 0;
        __syncthreads();
        sp[t] += v;
        __syncthreads();
    }
    int run = sp[t] - own;                     // exclusive prefix of chunk
    for (int i = lo; i < hi; i++) {
        g_off[i] = run;
        run += g_cnt[i];
    }
}

__global__ void fill_kernel(const int* __restrict__ ei,
                            const int* __restrict__ xids) {
    int e = blockIdx.x * blockDim.x + threadIdx.x;
    if (e >= N_EDGES) return;
    int dst = ei[N_EDGES + e];
    int id  = __ldg(xids + ei[e]);
    int pos = atomicAdd(&g_cur[dst], 1);
    g_csr[g_off[dst] + pos] = id;
}

// ---------------------------------------------------------------------------
// K6: warp-per-dst gather: agg[dst] = (sum embWl_bf[id]) / max(deg,1).
// Ids prefetched coalesced + shfl broadcast; bf16 rows (256B) -> fp32 acc.
// No atomics; every node written exactly once (deg-0 nodes write zeros).
// ---------------------------------------------------------------------------
__global__ void __launch_bounds__(256)
gather_kernel() {
    int w    = (blockIdx.x * blockDim.x + threadIdx.x) >> 5;
    int lane = threadIdx.x & 31;
    if (w >= N_NODES) return;
    const int off = g_off[w];
    const int cnt = g_cnt[w];

    float4 acc = make_float4(0.f, 0.f, 0.f, 0.f);
    for (int base = 0; base < cnt; base += 32) {
        int m = min(32, cnt - base);
        int id_l = (base + lane < cnt) ? __ldg(g_csr + off + base + lane) : 0;
        int j = 0;
        for (; j + 2 <= m; j += 2) {
            int id0 = __shfl_sync(0xFFFFFFFFu, id_l, j);
            int id1 = __shfl_sync(0xFFFFFFFFu, id_l, j + 1);
            uint2 u0 = __ldg(reinterpret_cast<const uint2*>(
                g_embWl_bf + (size_t)id0 * DIM) + lane);
            uint2 u1 = __ldg(reinterpret_cast<const uint2*>(
                g_embWl_bf + (size_t)id1 * DIM) + lane);
            float2 a0 = __bfloat1622float2(*reinterpret_cast<__nv_bfloat162*>(&u0.x));
            float2 b0 = __bfloat1622float2(*reinterpret_cast<__nv_bfloat162*>(&u0.y));
            float2 a1 = __bfloat1622float2(*reinterpret_cast<__nv_bfloat162*>(&u1.x));
            float2 b1 = __bfloat1622float2(*reinterpret_cast<__nv_bfloat162*>(&u1.y));
            acc.x += a0.x + a1.x;  acc.y += a0.y + a1.y;
            acc.z += b0.x + b1.x;  acc.w += b0.y + b1.y;
        }
        if (j < m) {
            int id0 = __shfl_sync(0xFFFFFFFFu, id_l, j);
            uint2 u0 = __ldg(reinterpret_cast<const uint2*>(
                g_embWl_bf + (size_t)id0 * DIM) + lane);
            float2 a0 = __bfloat1622float2(*reinterpret_cast<__nv_bfloat162*>(&u0.x));
            float2 b0 = __bfloat1622float2(*reinterpret_cast<__nv_bfloat162*>(&u0.y));
            acc.x += a0.x;  acc.y += a0.y;  acc.z += b0.x;  acc.w += b0.y;
        }
    }
    float sc = __fdividef(1.f, fmaxf((float)cnt, 1.f));
    acc.x *= sc; acc.y *= sc; acc.z *= sc; acc.w *= sc;
    *reinterpret_cast<float4*>(g_agg + (size_t)w * DIM + lane * 4) = acc;
}

// ---------------------------------------------------------------------------
// K7: fused pool: h = relu(agg + embWr[id] + bl), per-graph max/mean,
// final 256-dot + sigmoid. One block (128 thr) per graph.
// ---------------------------------------------------------------------------
__global__ void __launch_bounds__(128)
pool_kernel(const int* __restrict__ xids,
            const float* __restrict__ bl,
            const float* __restrict__ w1,
            const float* __restrict__ b1,
            float* __restrict__ out) {
    __shared__ float sred[4];
    const int g = blockIdx.x;
    const int c = threadIdx.x;
    const int start = g_seg[g];
    const int end   = (g == NUM_GRAPHS - 1) ? N_NODES : g_seg[g + 1];
    const float cnt = (float)(end - start);
    const float blc = bl[c];

    float maxj = 0.f, sumj = 0.f;   // relu >= 0: 0 is valid max identity
    int n = start;
    for (; n + 4 <= end; n += 4) {
        float a[4], e[4];
#pragma unroll
        for (int m = 0; m < 4; m++) {
            int nn = n + m;
            a[m] = g_agg[(size_t)nn * DIM + c];
            e[m] = g_embWr[(size_t)__ldg(xids + nn) * DIM + c];
        }
#pragma unroll
        for (int m = 0; m < 4; m++) {
            float hv = fmaxf(a[m] + e[m] + blc, 0.f);
            maxj = fmaxf(maxj, hv);
            sumj += hv;
        }
    }
    for (; n < end; n++) {
        float hv = fmaxf(g_agg[(size_t)n * DIM + c]
                         + g_embWr[(size_t)__ldg(xids + n) * DIM + c] + blc, 0.f);
        maxj = fmaxf(maxj, hv);
        sumj += hv;
    }

    float val = maxj * w1[c] + (sumj / cnt) * w1[DIM + c];
#pragma unroll
    for (int off = 16; off > 0; off >>= 1)
        val += __shfl_down_sync(0xFFFFFFFFu, val, off);
    if ((c & 31) == 0) sred[c >> 5] = val;
    __syncthreads();
    if (c == 0) {
        float tot = sred[0] + sred[1] + sred[2] + sred[3] + b1[0];
        out[g] = 1.f / (1.f + expf(-tot));
    }
}

// ---------------------------------------------------------------------------
extern "C" void kernel_launch(void* const* d_in, const int* in_sizes, int n_in,
                              void* d_out, int out_size) {
    const int*   xids  = (const int*)d_in[0];
    const int*   ei    = (const int*)d_in[1];
    const int*   batch = (const int*)d_in[2];
    const float* emb   = (const float*)d_in[3];
    const float* Wl    = (const float*)d_in[4];
    const float* bl    = (const float*)d_in[5];
    const float* Wr    = (const float*)d_in[6];
    const float* w1    = (const float*)d_in[7];
    const float* b1    = (const float*)d_in[8];
    float*       out   = (float*)d_out;

    const int eb = (N_EDGES + 255) / 256;
    zero_kernel<<<128, 256>>>();
    seg_kernel<<<256, 256>>>(batch);
    static int attr_set = 0;
    if (!attr_set) {
        cudaFuncSetAttribute(precompute_kernel,
                             cudaFuncAttributeMaxDynamicSharedMemorySize, P_SMEM);
        attr_set = 1;
    }
    precompute_kernel<<<PTILES, 128, P_SMEM>>>(emb, Wl, Wr);
    hist_kernel<<<eb, 256>>>(ei);
    scan_kernel<<<1, 1024>>>();
    fill_kernel<<<eb, 256>>>(ei, xids);
    gather_kernel<<<(N_NODES * 32 + 255) / 256, 256>>>();
    pool_kernel<<<NUM_GRAPHS, 128>>>(xids, bl, w1, b1, out);
}

// round 16
// speedup vs baseline: 1.1333x; 1.1333x over previous
#include <cuda_runtime.h>
#include <cuda_bf16.h>
#include <math.h>
#include <stdint.h>

#define N_NODES    50000
#define N_EDGES    600000
#define DIM        128
#define VOCAB      20215
#define NUM_GRAPHS 512
#define PTILES     ((VOCAB + 63) / 64)     // 316
#define ROWB2      272                     // 128 bf16 = 256B + 16 pad; LDSM conflict-free
#define P_OFF_W    0                       // 256 x 272 = 69632
#define P_OFF_A    69632                   // 64 x 272  = 17408
#define P_SMEM     (69632 + 17408)

// Scratch (device globals: allocation inside kernel_launch is forbidden)
__device__ __align__(16) float g_agg[N_NODES * DIM];            // sum embWl[src] per dst
__device__ __align__(16) __nv_bfloat16 g_embWl_bf[VOCAB * DIM]; // emb @ Wl^T, bf16
__device__ __align__(16) float g_embWr[VOCAB * DIM];            // emb @ Wr^T, fp32
__device__ float g_deg[N_NODES];
__device__ int   g_seg[NUM_GRAPHS];

// ---- warp-MMA helpers (sm_80-era PTX, valid for compute_100) ---------------
__device__ __forceinline__ uint32_t smem_u32(const void* p) {
    uint32_t a;
    asm("{ .reg .u64 t; cvta.to.shared.u64 t, %1; cvt.u32.u64 %0, t; }"
        : "=r"(a) : "l"(p));
    return a;
}
__device__ __forceinline__ void ldsm_x4(uint32_t* r, uint32_t addr) {
    asm volatile("ldmatrix.sync.aligned.m8n8.x4.shared.b16 {%0,%1,%2,%3}, [%4];"
                 : "=r"(r[0]), "=r"(r[1]), "=r"(r[2]), "=r"(r[3]) : "r"(addr));
}
__device__ __forceinline__ void ldsm_x2(uint32_t* r, uint32_t addr) {
    asm volatile("ldmatrix.sync.aligned.m8n8.x2.shared.b16 {%0,%1}, [%2];"
                 : "=r"(r[0]), "=r"(r[1]) : "r"(addr));
}
__device__ __forceinline__ void mma16816(float* c, const uint32_t* a, const uint32_t* b) {
    asm volatile(
        "mma.sync.aligned.m16n8k16.row.col.f32.bf16.bf16.f32 "
        "{%0,%1,%2,%3}, {%4,%5,%6,%7}, {%8,%9}, {%0,%1,%2,%3};"
        : "+f"(c[0]), "+f"(c[1]), "+f"(c[2]), "+f"(c[3])
        : "r"(a[0]), "r"(a[1]), "r"(a[2]), "r"(a[3]), "r"(b[0]), "r"(b[1]));
}
__device__ __forceinline__ uint4 pack_bf16x8(const float* f) {
    __nv_bfloat162 h0 = __float22bfloat162_rn(make_float2(f[0], f[1]));
    __nv_bfloat162 h1 = __float22bfloat162_rn(make_float2(f[2], f[3]));
    __nv_bfloat162 h2 = __float22bfloat162_rn(make_float2(f[4], f[5]));
    __nv_bfloat162 h3 = __float22bfloat162_rn(make_float2(f[6], f[7]));
    uint4 u;
    u.x = *reinterpret_cast<uint32_t*>(&h0);
    u.y = *reinterpret_cast<uint32_t*>(&h1);
    u.z = *reinterpret_cast<uint32_t*>(&h2);
    u.w = *reinterpret_cast<uint32_t*>(&h3);
    return u;
}

// ---------------------------------------------------------------------------
__global__ void zero_kernel() {
    int i = blockIdx.x * blockDim.x + threadIdx.x;
    int stride = gridDim.x * blockDim.x;
    float4* p = reinterpret_cast<float4*>(g_agg);
    const int n4 = N_NODES * DIM / 4;
    for (int k = i; k < n4; k += stride) p[k] = make_float4(0.f, 0.f, 0.f, 0.f);
    for (int k = i; k < N_NODES; k += stride) g_deg[k] = 0.f;
}

__global__ void seg_kernel(const int* __restrict__ batch) {
    int i = blockIdx.x * blockDim.x + threadIdx.x;
    int stride = gridDim.x * blockDim.x;
    for (; i < N_NODES; i += stride) {
        if (i == 0 || batch[i] != batch[i - 1]) g_seg[batch[i]] = i;
    }
}

// ---------------------------------------------------------------------------
// K2: precompute embWl (bf16) and embWr (fp32) via bf16 warp-MMA.
// ---------------------------------------------------------------------------
__global__ void __launch_bounds__(128, 1)
precompute_kernel(const float* __restrict__ emb,
                  const float* __restrict__ Wl,
                  const float* __restrict__ Wr) {
    extern __shared__ char dyn[];
    char* sW = dyn + P_OFF_W;            // [256 n][128 k] bf16, stride 272B
    char* sA = dyn + P_OFF_A;            // [64 v][128 k] bf16, stride 272B

    const int t    = threadIdx.x;
    const int wid  = t >> 5;
    const int lane = t & 31;

    // Stage W' = [Wl; Wr]: 256 rows x 128 k
    for (int j = 0; j < 32; j++) {
        int chunk = t + j * 128;
        int n  = chunk >> 4;
        int ck = (chunk & 15) * 8;
        const float* src = (n < DIM) ? (Wl + n * DIM + ck)
                                     : (Wr + (n - DIM) * DIM + ck);
        float f[8];
        *reinterpret_cast<float4*>(f)     = *reinterpret_cast<const float4*>(src);
        *reinterpret_cast<float4*>(f + 4) = *reinterpret_cast<const float4*>(src + 4);
        *reinterpret_cast<uint4*>(sW + n * ROWB2 + ck * 2) = pack_bf16x8(f);
    }

    const int tbase = blockIdx.x * 64;
    for (int j = 0; j < 8; j++) {
        int chunk = t + j * 128;
        int r  = chunk >> 4;
        int ck = (chunk & 15) * 8;
        int v  = tbase + r;
        float f[8];
#pragma unroll
        for (int i = 0; i < 8; i++) f[i] = 0.f;
        if (v < VOCAB) {
            const float4* s4 = reinterpret_cast<const float4*>(
                emb + (size_t)v * DIM + ck);
            *reinterpret_cast<float4*>(f)     = s4[0];
            *reinterpret_cast<float4*>(f + 4) = s4[1];
        }
        *reinterpret_cast<uint4*>(sA + r * ROWB2 + ck * 2) = pack_bf16x8(f);
    }
    __syncthreads();

    const uint32_t sA_base = smem_u32(sA);
    const uint32_t sW_base = smem_u32(sW);
    const uint32_t a_lane_off = (uint32_t)((wid * 16 + (lane & 15)) * ROWB2
                                           + ((lane >> 4) * 8) * 2);
    const uint32_t b_lane_off = (uint32_t)((lane & 7) * ROWB2
                                           + ((lane >> 3) & 1) * 16);

    float acc[32][4];
#pragma unroll
    for (int n = 0; n < 32; n++)
#pragma unroll
        for (int i = 0; i < 4; i++) acc[n][i] = 0.f;

    for (int kk = 0; kk < 8; kk++) {
        uint32_t a[4];
        ldsm_x4(a, sA_base + a_lane_off + kk * 32);
#pragma unroll
        for (int n = 0; n < 32; n++) {
            uint32_t b[2];
            ldsm_x2(b, sW_base + (uint32_t)(n * 8 * ROWB2) + b_lane_off + kk * 32);
            mma16816(acc[n], a, b);
        }
    }

    // cols 0..127 -> embWl (bf16), 128..255 -> embWr (fp32)
    const int row = wid * 16 + (lane >> 2);
    const int v0 = tbase + row;
    const int v1 = v0 + 8;
#pragma unroll
    for (int n = 0; n < 32; n++) {
        int col = (n & 15) * 8 + (lane & 3) * 2;
        if (n < 16) {
            __nv_bfloat162 p0 = __float22bfloat162_rn(
                make_float2(acc[n][0], acc[n][1]));
            __nv_bfloat162 p1 = __float22bfloat162_rn(
                make_float2(acc[n][2], acc[n][3]));
            if (v0 < VOCAB)
                *reinterpret_cast<__nv_bfloat162*>(
                    &g_embWl_bf[(size_t)v0 * DIM + col]) = p0;
            if (v1 < VOCAB)
                *reinterpret_cast<__nv_bfloat162*>(
                    &g_embWl_bf[(size_t)v1 * DIM + col]) = p1;
        } else {
            if (v0 < VOCAB)
                *reinterpret_cast<float2*>(g_embWr + (size_t)v0 * DIM + col) =
                    make_float2(acc[n][0], acc[n][1]);
            if (v1 < VOCAB)
                *reinterpret_cast<float2*>(g_embWr + (size_t)v1 * DIM + col) =
                    make_float2(acc[n][2], acc[n][3]);
        }
    }
}

// ---------------------------------------------------------------------------
// K3: edge scatter of PRE-MULTIPLIED bf16 rows: agg[dst] += embWl_bf[x[src]].
// Warp per edge: 256B coalesced bf16 row read (8B/lane), fp32 convert,
// red.global.add.v4.f32 (write-only reduction, no return trip).
// ---------------------------------------------------------------------------
__global__ void scatter_kernel(const int* __restrict__ ei,
                               const int* __restrict__ xids) {
    int warp = (blockIdx.x * blockDim.x + threadIdx.x) >> 5;
    int lane = threadIdx.x & 31;
    if (warp >= N_EDGES) return;
    int src = __ldg(ei + warp);
    int dst = __ldg(ei + N_EDGES + warp);
    int id  = __ldg(xids + src);
    uint2 u = __ldg(reinterpret_cast<const uint2*>(
        g_embWl_bf + (size_t)id * DIM) + lane);
    float2 a = __bfloat1622float2(*reinterpret_cast<__nv_bfloat162*>(&u.x));
    float2 b = __bfloat1622float2(*reinterpret_cast<__nv_bfloat162*>(&u.y));
    float* outp = g_agg + (size_t)dst * DIM + lane * 4;
    asm volatile("red.global.add.v4.f32 [%0], {%1,%2,%3,%4};"
                 :: "l"(outp), "f"(a.x), "f"(a.y), "f"(b.x), "f"(b.y)
                 : "memory");
    if (lane == 0) atomicAdd(g_deg + dst, 1.0f);
}

// ---------------------------------------------------------------------------
// K4: fused pool: h = relu(agg/deg + embWr[id] + bl), per-graph max/mean,
// final 256-dot + sigmoid. One block (128 thr) per graph; thread c = column.
// ---------------------------------------------------------------------------
__global__ void __launch_bounds__(128)
pool_kernel(const int* __restrict__ xids,
            const float* __restrict__ bl,
            const float* __restrict__ w1,
            const float* __restrict__ b1,
            float* __restrict__ out) {
    __shared__ float sred[4];
    const int g = blockIdx.x;
    const int c = threadIdx.x;
    const int start = g_seg[g];
    const int end   = (g == NUM_GRAPHS - 1) ? N_NODES : g_seg[g + 1];
    const float cnt = (float)(end - start);
    const float blc = bl[c];

    float maxj = 0.f, sumj = 0.f;   // relu >= 0: 0 is valid max identity
    int n = start;
    for (; n + 4 <= end; n += 4) {
        float a[4], e[4], d[4];
#pragma unroll
        for (int m = 0; m < 4; m++) {
            int nn = n + m;
            a[m] = g_agg[(size_t)nn * DIM + c];
            e[m] = g_embWr[(size_t)__ldg(xids + nn) * DIM + c];
            d[m] = g_deg[nn];
        }
#pragma unroll
        for (int m = 0; m < 4; m++) {
            float sc = __fdividef(1.f, fmaxf(d[m], 1.f));
            float hv = fmaxf(fmaf(a[m], sc, e[m]) + blc, 0.f);
            maxj = fmaxf(maxj, hv);
            sumj += hv;
        }
    }
    for (; n < end; n++) {
        float sc = __fdividef(1.f, fmaxf(g_deg[n], 1.f));
        float hv = fmaxf(fmaf(g_agg[(size_t)n * DIM + c], sc,
                              g_embWr[(size_t)__ldg(xids + n) * DIM + c]) + blc,
                         0.f);
        maxj = fmaxf(maxj, hv);
        sumj += hv;
    }

    float val = maxj * w1[c] + (sumj / cnt) * w1[DIM + c];
#pragma unroll
    for (int off = 16; off > 0; off >>= 1)
        val += __shfl_down_sync(0xFFFFFFFFu, val, off);
    if ((c & 31) == 0) sred[c >> 5] = val;
    __syncthreads();
    if (c == 0) {
        float tot = sred[0] + sred[1] + sred[2] + sred[3] + b1[0];
        out[g] = 1.f / (1.f + expf(-tot));
    }
}

// ---------------------------------------------------------------------------
extern "C" void kernel_launch(void* const* d_in, const int* in_sizes, int n_in,
                              void* d_out, int out_size) {
    const int*   xids  = (const int*)d_in[0];
    const int*   ei    = (const int*)d_in[1];
    const int*   batch = (const int*)d_in[2];
    const float* emb   = (const float*)d_in[3];
    const float* Wl    = (const float*)d_in[4];
    const float* bl    = (const float*)d_in[5];
    const float* Wr    = (const float*)d_in[6];
    const float* w1    = (const float*)d_in[7];
    const float* b1    = (const float*)d_in[8];
    float*       out   = (float*)d_out;

    zero_kernel<<<2048, 256>>>();
    seg_kernel<<<256, 256>>>(batch);
    static int attr_set = 0;
    if (!attr_set) {
        cudaFuncSetAttribute(precompute_kernel,
                             cudaFuncAttributeMaxDynamicSharedMemorySize, P_SMEM);
        attr_set = 1;
    }
    precompute_kernel<<<PTILES, 128, P_SMEM>>>(emb, Wl, Wr);
    {
        long long threads = (long long)N_EDGES * 32;
        int blocks = (int)((threads + 255) / 256);
        scatter_kernel<<<blocks, 256>>>(ei, xids);
    }
    pool_kernel<<<NUM_GRAPHS, 128>>>(xids, bl, w1, b1, out);
}

// round 17
// speedup vs baseline: 1.6187x; 1.4283x over previous
#include <cuda_runtime.h>
#include <cuda_bf16.h>
#include <math.h>
#include <stdint.h>

#define N_NODES    50000
#define N_EDGES    600000
#define DIM        128
#define VOCAB      20215
#define NUM_GRAPHS 512
#define PTILES     ((VOCAB + 63) / 64)     // 316
#define ROWB2      272                     // 128 bf16 = 256B + 16 pad; LDSM conflict-free
#define P_OFF_W    0                       // 256 x 272 = 69632
#define P_OFF_A    69632                   // 64 x 272  = 17408
#define P_SMEM     (69632 + 17408)

// Scratch (device globals: allocation inside kernel_launch is forbidden)
__device__ __align__(16) __nv_bfloat16 g_agg_bf[N_NODES * DIM]; // bf16 accumulators
__device__ __align__(16) __nv_bfloat16 g_embWl_bf[VOCAB * DIM]; // emb @ Wl^T, bf16
__device__ __align__(16) float g_embWr[VOCAB * DIM];            // emb @ Wr^T, fp32
__device__ float g_deg[N_NODES];
__device__ int   g_seg[NUM_GRAPHS];

// ---- warp-MMA helpers (sm_80-era PTX, valid for compute_100) ---------------
__device__ __forceinline__ uint32_t smem_u32(const void* p) {
    uint32_t a;
    asm("{ .reg .u64 t; cvta.to.shared.u64 t, %1; cvt.u32.u64 %0, t; }"
        : "=r"(a) : "l"(p));
    return a;
}
__device__ __forceinline__ void ldsm_x4(uint32_t* r, uint32_t addr) {
    asm volatile("ldmatrix.sync.aligned.m8n8.x4.shared.b16 {%0,%1,%2,%3}, [%4];"
                 : "=r"(r[0]), "=r"(r[1]), "=r"(r[2]), "=r"(r[3]) : "r"(addr));
}
__device__ __forceinline__ void ldsm_x2(uint32_t* r, uint32_t addr) {
    asm volatile("ldmatrix.sync.aligned.m8n8.x2.shared.b16 {%0,%1}, [%2];"
                 : "=r"(r[0]), "=r"(r[1]) : "r"(addr));
}
__device__ __forceinline__ void mma16816(float* c, const uint32_t* a, const uint32_t* b) {
    asm volatile(
        "mma.sync.aligned.m16n8k16.row.col.f32.bf16.bf16.f32 "
        "{%0,%1,%2,%3}, {%4,%5,%6,%7}, {%8,%9}, {%0,%1,%2,%3};"
        : "+f"(c[0]), "+f"(c[1]), "+f"(c[2]), "+f"(c[3])
        : "r"(a[0]), "r"(a[1]), "r"(a[2]), "r"(a[3]), "r"(b[0]), "r"(b[1]));
}
__device__ __forceinline__ uint4 pack_bf16x8(const float* f) {
    __nv_bfloat162 h0 = __float22bfloat162_rn(make_float2(f[0], f[1]));
    __nv_bfloat162 h1 = __float22bfloat162_rn(make_float2(f[2], f[3]));
    __nv_bfloat162 h2 = __float22bfloat162_rn(make_float2(f[4], f[5]));
    __nv_bfloat162 h3 = __float22bfloat162_rn(make_float2(f[6], f[7]));
    uint4 u;
    u.x = *reinterpret_cast<uint32_t*>(&h0);
    u.y = *reinterpret_cast<uint32_t*>(&h1);
    u.z = *reinterpret_cast<uint32_t*>(&h2);
    u.w = *reinterpret_cast<uint32_t*>(&h3);
    return u;
}

// ---------------------------------------------------------------------------
__global__ void zero_kernel() {
    int i = blockIdx.x * blockDim.x + threadIdx.x;
    int stride = gridDim.x * blockDim.x;
    uint4* p = reinterpret_cast<uint4*>(g_agg_bf);
    const int n16 = N_NODES * DIM * 2 / 16;         // bf16 zero == 0x0000
    uint4 z = make_uint4(0u, 0u, 0u, 0u);
    for (int k = i; k < n16; k += stride) p[k] = z;
    for (int k = i; k < N_NODES; k += stride) g_deg[k] = 0.f;
}

__global__ void seg_kernel(const int* __restrict__ batch) {
    int i = blockIdx.x * blockDim.x + threadIdx.x;
    int stride = gridDim.x * blockDim.x;
    for (; i < N_NODES; i += stride) {
        if (i == 0 || batch[i] != batch[i - 1]) g_seg[batch[i]] = i;
    }
}

// ---------------------------------------------------------------------------
// K2: precompute embWl (bf16) and embWr (fp32) via bf16 warp-MMA.
// ---------------------------------------------------------------------------
__global__ void __launch_bounds__(128, 1)
precompute_kernel(const float* __restrict__ emb,
                  const float* __restrict__ Wl,
                  const float* __restrict__ Wr) {
    extern __shared__ char dyn[];
    char* sW = dyn + P_OFF_W;            // [256 n][128 k] bf16, stride 272B
    char* sA = dyn + P_OFF_A;            // [64 v][128 k] bf16, stride 272B

    const int t    = threadIdx.x;
    const int wid  = t >> 5;
    const int lane = t & 31;

    // Stage W' = [Wl; Wr]: 256 rows x 128 k
    for (int j = 0; j < 32; j++) {
        int chunk = t + j * 128;
        int n  = chunk >> 4;
        int ck = (chunk & 15) * 8;
        const float* src = (n < DIM) ? (Wl + n * DIM + ck)
                                     : (Wr + (n - DIM) * DIM + ck);
        float f[8];
        *reinterpret_cast<float4*>(f)     = *reinterpret_cast<const float4*>(src);
        *reinterpret_cast<float4*>(f + 4) = *reinterpret_cast<const float4*>(src + 4);
        *reinterpret_cast<uint4*>(sW + n * ROWB2 + ck * 2) = pack_bf16x8(f);
    }

    const int tbase = blockIdx.x * 64;
    for (int j = 0; j < 8; j++) {
        int chunk = t + j * 128;
        int r  = chunk >> 4;
        int ck = (chunk & 15) * 8;
        int v  = tbase + r;
        float f[8];
#pragma unroll
        for (int i = 0; i < 8; i++) f[i] = 0.f;
        if (v < VOCAB) {
            const float4* s4 = reinterpret_cast<const float4*>(
                emb + (size_t)v * DIM + ck);
            *reinterpret_cast<float4*>(f)     = s4[0];
            *reinterpret_cast<float4*>(f + 4) = s4[1];
        }
        *reinterpret_cast<uint4*>(sA + r * ROWB2 + ck * 2) = pack_bf16x8(f);
    }
    __syncthreads();

    const uint32_t sA_base = smem_u32(sA);
    const uint32_t sW_base = smem_u32(sW);
    const uint32_t a_lane_off = (uint32_t)((wid * 16 + (lane & 15)) * ROWB2
                                           + ((lane >> 4) * 8) * 2);
    const uint32_t b_lane_off = (uint32_t)((lane & 7) * ROWB2
                                           + ((lane >> 3) & 1) * 16);

    float acc[32][4];
#pragma unroll
    for (int n = 0; n < 32; n++)
#pragma unroll
        for (int i = 0; i < 4; i++) acc[n][i] = 0.f;

    for (int kk = 0; kk < 8; kk++) {
        uint32_t a[4];
        ldsm_x4(a, sA_base + a_lane_off + kk * 32);
#pragma unroll
        for (int n = 0; n < 32; n++) {
            uint32_t b[2];
            ldsm_x2(b, sW_base + (uint32_t)(n * 8 * ROWB2) + b_lane_off + kk * 32);
            mma16816(acc[n], a, b);
        }
    }

    // cols 0..127 -> embWl (bf16), 128..255 -> embWr (fp32)
    const int row = wid * 16 + (lane >> 2);
    const int v0 = tbase + row;
    const int v1 = v0 + 8;
#pragma unroll
    for (int n = 0; n < 32; n++) {
        int col = (n & 15) * 8 + (lane & 3) * 2;
        if (n < 16) {
            __nv_bfloat162 p0 = __float22bfloat162_rn(
                make_float2(acc[n][0], acc[n][1]));
            __nv_bfloat162 p1 = __float22bfloat162_rn(
                make_float2(acc[n][2], acc[n][3]));
            if (v0 < VOCAB)
                *reinterpret_cast<__nv_bfloat162*>(
                    &g_embWl_bf[(size_t)v0 * DIM + col]) = p0;
            if (v1 < VOCAB)
                *reinterpret_cast<__nv_bfloat162*>(
                    &g_embWl_bf[(size_t)v1 * DIM + col]) = p1;
        } else {
            if (v0 < VOCAB)
                *reinterpret_cast<float2*>(g_embWr + (size_t)v0 * DIM + col) =
                    make_float2(acc[n][0], acc[n][1]);
            if (v1 < VOCAB)
                *reinterpret_cast<float2*>(g_embWr + (size_t)v1 * DIM + col) =
                    make_float2(acc[n][2], acc[n][3]);
        }
    }
}

// ---------------------------------------------------------------------------
// K3: edge scatter, bf16 accumulators. 2 edges per warp; 16 lanes per edge,
// each lane moves 16B (8 bf16) from embWl_bf row straight into a
// red.global.add.noftz.v4.bf16x2 — no converts, half the red-lanes of v4.f32.
// ---------------------------------------------------------------------------
__global__ void scatter_kernel(const int* __restrict__ ei,
                               const int* __restrict__ xids) {
    int idx  = blockIdx.x * blockDim.x + threadIdx.x;
    int lane = threadIdx.x & 31;
    int e    = ((idx >> 5) << 1) + (lane >> 4);    // 2 edges per warp
    if (e >= N_EDGES) return;
    int sub = lane & 15;
    int src = __ldg(ei + e);
    int dst = __ldg(ei + N_EDGES + e);
    int id  = __ldg(xids + src);
    uint4 u = __ldg(reinterpret_cast<const uint4*>(
        g_embWl_bf + (size_t)id * DIM) + sub);
    __nv_bfloat16* outp = g_agg_bf + (size_t)dst * DIM + sub * 8;
    asm volatile("red.global.add.noftz.v4.bf16x2 [%0], {%1,%2,%3,%4};"
                 :: "l"(outp), "r"(u.x), "r"(u.y), "r"(u.z), "r"(u.w)
                 : "memory");
    if (sub == 0) atomicAdd(g_deg + dst, 1.0f);
}

// ---------------------------------------------------------------------------
// K4: fused pool: h = relu(agg/deg + embWr[id] + bl), per-graph max/mean,
// final 256-dot + sigmoid. One block (128 thr) per graph; thread c = column.
// ---------------------------------------------------------------------------
__global__ void __launch_bounds__(128)
pool_kernel(const int* __restrict__ xids,
            const float* __restrict__ bl,
            const float* __restrict__ w1,
            const float* __restrict__ b1,
            float* __restrict__ out) {
    __shared__ float sred[4];
    const int g = blockIdx.x;
    const int c = threadIdx.x;
    const int start = g_seg[g];
    const int end   = (g == NUM_GRAPHS - 1) ? N_NODES : g_seg[g + 1];
    const float cnt = (float)(end - start);
    const float blc = bl[c];

    float maxj = 0.f, sumj = 0.f;   // relu >= 0: 0 is valid max identity
    int n = start;
    for (; n + 4 <= end; n += 4) {
        float a[4], e[4], d[4];
#pragma unroll
        for (int m = 0; m < 4; m++) {
            int nn = n + m;
            a[m] = __bfloat162float(g_agg_bf[(size_t)nn * DIM + c]);
            e[m] = g_embWr[(size_t)__ldg(xids + nn) * DIM + c];
            d[m] = g_deg[nn];
        }
#pragma unroll
        for (int m = 0; m < 4; m++) {
            float sc = __fdividef(1.f, fmaxf(d[m], 1.f));
            float hv = fmaxf(fmaf(a[m], sc, e[m]) + blc, 0.f);
            maxj = fmaxf(maxj, hv);
            sumj += hv;
        }
    }
    for (; n < end; n++) {
        float sc = __fdividef(1.f, fmaxf(g_deg[n], 1.f));
        float hv = fmaxf(fmaf(__bfloat162float(g_agg_bf[(size_t)n * DIM + c]), sc,
                              g_embWr[(size_t)__ldg(xids + n) * DIM + c]) + blc,
                         0.f);
        maxj = fmaxf(maxj, hv);
        sumj += hv;
    }

    float val = maxj * w1[c] + (sumj / cnt) * w1[DIM + c];
#pragma unroll
    for (int off = 16; off > 0; off >>= 1)
        val += __shfl_down_sync(0xFFFFFFFFu, val, off);
    if ((c & 31) == 0) sred[c >> 5] = val;
    __syncthreads();
    if (c == 0) {
        float tot = sred[0] + sred[1] + sred[2] + sred[3] + b1[0];
        out[g] = 1.f / (1.f + expf(-tot));
    }
}

// ---------------------------------------------------------------------------
extern "C" void kernel_launch(void* const* d_in, const int* in_sizes, int n_in,
                              void* d_out, int out_size) {
    const int*   xids  = (const int*)d_in[0];
    const int*   ei    = (const int*)d_in[1];
    const int*   batch = (const int*)d_in[2];
    const float* emb   = (const float*)d_in[3];
    const float* Wl    = (const float*)d_in[4];
    const float* bl    = (const float*)d_in[5];
    const float* Wr    = (const float*)d_in[6];
    const float* w1    = (const float*)d_in[7];
    const float* b1    = (const float*)d_in[8];
    float*       out   = (float*)d_out;

    zero_kernel<<<2048, 256>>>();
    seg_kernel<<<256, 256>>>(batch);
    static int attr_set = 0;
    if (!attr_set) {
        cudaFuncSetAttribute(precompute_kernel,
                             cudaFuncAttributeMaxDynamicSharedMemorySize, P_SMEM);
        attr_set = 1;
    }
    precompute_kernel<<<PTILES, 128, P_SMEM>>>(emb, Wl, Wr);
    {
        // 2 edges per warp -> 300000 warps
        long long threads = (long long)(N_EDGES / 2) * 32;
        int blocks = (int)((threads + 255) / 256);
        scatter_kernel<<<blocks, 256>>>(ei, xids);
    }
    pool_kernel<<<NUM_GRAPHS, 128>>>(xids, bl, w1, b1, out);
}